// round 1
// baseline (speedup 1.0000x reference)
#include <cuda_runtime.h>
#include <cstdint>

#define NN   100000
#define EE   1600000
#define DIN  48
#define DOUT 16
#define DC   32   // concatenated output dim (mu | logstd)

// Scratch (allocation-free contract: __device__ globals)
__device__ unsigned int g_cnt[NN];
__device__ float        g_dinv[NN];
__device__ float        g_y[(size_t)NN * DC];   // x @ [W_mu | W_logstd], 12.8 MB (L2-resident)

// ---------------------------------------------------------------------------
// Kernel 1: zero the degree counters (graph replays -> must re-init each call)
// ---------------------------------------------------------------------------
__global__ void k_init_cnt() {
    int i = blockIdx.x * blockDim.x + threadIdx.x;
    if (i < NN) g_cnt[i] = 0u;
}

// ---------------------------------------------------------------------------
// Kernel 2: in-degree count on dst (deg = 1 + count, the +1 applied later)
// ---------------------------------------------------------------------------
__global__ void k_count(const int* __restrict__ dst) {
    int i = blockIdx.x * blockDim.x + threadIdx.x;
    if (i < EE) atomicAdd(&g_cnt[dst[i]], 1u);
}

// ---------------------------------------------------------------------------
// Kernel 3: dinv + projection y = x @ Wcat, and initialize out with the
// self-loop term + bias:  out[n] = y[n] * dinv(n)^2 + b
// 8 threads per node, each producing a float4 (4 of the 32 output cols).
// ---------------------------------------------------------------------------
__global__ void k_project(const float* __restrict__ x,
                          const float* __restrict__ Wmu,
                          const float* __restrict__ bmu,
                          const float* __restrict__ Wls,
                          const float* __restrict__ bls,
                          float* __restrict__ out) {
    __shared__ float sW[DIN][DC];   // 6 KB, concatenated weights, k-major
    __shared__ float sb[DC];

    int tid = threadIdx.x;  // 256
    for (int i = tid; i < DIN * DOUT; i += blockDim.x) {
        int k = i / DOUT, j = i % DOUT;
        sW[k][j]      = Wmu[i];
        sW[k][j + 16] = Wls[i];
    }
    if (tid < DOUT) { sb[tid] = bmu[tid]; sb[tid + 16] = bls[tid]; }
    __syncthreads();

    int g  = blockIdx.x * blockDim.x + tid;
    int n  = g >> 3;            // node
    int j4 = (g & 7) * 4;       // output column group
    if (n >= NN) return;

    float dinv = rsqrtf(1.0f + (float)g_cnt[n]);
    if ((g & 7) == 0) g_dinv[n] = dinv;

    const float* xr = x + (size_t)n * DIN;
    float ax = 0.f, ay = 0.f, az = 0.f, aw = 0.f;
    #pragma unroll
    for (int k = 0; k < DIN; k++) {
        float xv = __ldg(xr + k);         // broadcast across the 8-thread group
        ax += xv * sW[k][j4 + 0];
        ay += xv * sW[k][j4 + 1];
        az += xv * sW[k][j4 + 2];
        aw += xv * sW[k][j4 + 3];
    }

    // stash projected row for the edge pass
    float4* yp = (float4*)(g_y + (size_t)n * DC + j4);
    *yp = make_float4(ax, ay, az, aw);

    // init output with self-loop term + bias
    float d2 = dinv * dinv;
    float4 o = make_float4(ax * d2 + sb[j4 + 0], ay * d2 + sb[j4 + 1],
                           az * d2 + sb[j4 + 2], aw * d2 + sb[j4 + 3]);
    float* obase = (j4 < DOUT)
        ? (out + (size_t)n * DOUT + j4)                          // mu half
        : (out + (size_t)NN * DOUT + (size_t)n * DOUT + (j4 - DOUT)); // logstd half
    *(float4*)obase = o;
}

// ---------------------------------------------------------------------------
// Kernel 4: edge scatter. One thread per edge; gathers the 128B projected row
// of src, scales by norm = dinv[src]*dinv[dst], and reduces into out[dst]
// with vectorized red.global.add.v4.f32 (no return -> REDG, 8 per edge).
// ---------------------------------------------------------------------------
__device__ __forceinline__ void red_add_v4(float* addr, float4 v) {
    asm volatile("red.global.add.v4.f32 [%0], {%1, %2, %3, %4};"
                 :: "l"(addr), "f"(v.x), "f"(v.y), "f"(v.z), "f"(v.w)
                 : "memory");
}

__global__ void k_edges(const int* __restrict__ src,
                        const int* __restrict__ dst,
                        float* __restrict__ out) {
    int e = blockIdx.x * blockDim.x + threadIdx.x;
    if (e >= EE) return;
    int s = __ldg(src + e);
    int d = __ldg(dst + e);
    float w = __ldg(&g_dinv[s]) * __ldg(&g_dinv[d]);

    const float4* yp = (const float4*)(g_y + (size_t)s * DC);
    float* omu = out + (size_t)d * DOUT;
    float* ols = out + (size_t)NN * DOUT + (size_t)d * DOUT;

    #pragma unroll
    for (int k = 0; k < 4; k++) {
        float4 v = __ldg(yp + k);
        v.x *= w; v.y *= w; v.z *= w; v.w *= w;
        red_add_v4(omu + k * 4, v);
    }
    #pragma unroll
    for (int k = 0; k < 4; k++) {
        float4 v = __ldg(yp + 4 + k);
        v.x *= w; v.y *= w; v.z *= w; v.w *= w;
        red_add_v4(ols + k * 4, v);
    }
}

// ---------------------------------------------------------------------------
extern "C" void kernel_launch(void* const* d_in, const int* in_sizes, int n_in,
                              void* d_out, int out_size) {
    const float* x   = (const float*)d_in[0];
    const int*   ei  = (const int*)  d_in[1];   // (2, E): row 0 = src, row 1 = dst
    const float* Wmu = (const float*)d_in[2];
    const float* bmu = (const float*)d_in[3];
    const float* Wls = (const float*)d_in[4];
    const float* bls = (const float*)d_in[5];
    float* out = (float*)d_out;

    const int* src = ei;
    const int* dst = ei + EE;

    k_init_cnt<<<(NN + 255) / 256, 256>>>();
    k_count   <<<(EE + 255) / 256, 256>>>(dst);
    k_project <<<(NN * 8 + 255) / 256, 256>>>(x, Wmu, bmu, Wls, bls, out);
    k_edges   <<<(EE + 255) / 256, 256>>>(src, dst, out);
}

// round 2
// speedup vs baseline: 1.5610x; 1.5610x over previous
#include <cuda_runtime.h>
#include <cstdint>

#define NN   100000
#define EE   1600000
#define DIN  48
#define DOUT 16
#define DC   32   // concatenated output dim (mu | logstd)

// Scratch (allocation-free contract: __device__ globals)
__device__ unsigned int g_cnt[NN];
__device__ float        g_dinv[NN];
__device__ __align__(128) float g_y[(size_t)NN * DC];  // x @ [W_mu|W_logstd]; row = 128B = 1 line

// ---------------------------------------------------------------------------
// Kernel 1: zero the degree counters (graph replays -> must re-init each call)
// ---------------------------------------------------------------------------
__global__ void k_init_cnt() {
    int i = blockIdx.x * blockDim.x + threadIdx.x;
    if (i < NN) g_cnt[i] = 0u;
}

// ---------------------------------------------------------------------------
// Kernel 2: in-degree count on dst (deg = 1 + count, the +1 applied later)
// ---------------------------------------------------------------------------
__global__ void k_count(const int* __restrict__ dst) {
    int i = blockIdx.x * blockDim.x + threadIdx.x;
    if (i < EE) atomicAdd(&g_cnt[dst[i]], 1u);
}

// ---------------------------------------------------------------------------
// Kernel 3: dinv + projection y = x @ Wcat, and initialize out with the
// self-loop term + bias:  out[n] = y[n] * dinv(n)^2 + b
// 8 threads per node, each producing a float4 (4 of the 32 output cols).
// ---------------------------------------------------------------------------
__global__ void k_project(const float* __restrict__ x,
                          const float* __restrict__ Wmu,
                          const float* __restrict__ bmu,
                          const float* __restrict__ Wls,
                          const float* __restrict__ bls,
                          float* __restrict__ out) {
    __shared__ float sW[DIN][DC];   // 6 KB, concatenated weights, k-major
    __shared__ float sb[DC];

    int tid = threadIdx.x;  // 256
    for (int i = tid; i < DIN * DOUT; i += blockDim.x) {
        int k = i / DOUT, j = i % DOUT;
        sW[k][j]      = Wmu[i];
        sW[k][j + 16] = Wls[i];
    }
    if (tid < DOUT) { sb[tid] = bmu[tid]; sb[tid + 16] = bls[tid]; }
    __syncthreads();

    int g  = blockIdx.x * blockDim.x + tid;
    int n  = g >> 3;            // node
    int j4 = (g & 7) * 4;       // output column group
    if (n >= NN) return;

    float dinv = rsqrtf(1.0f + (float)g_cnt[n]);
    if ((g & 7) == 0) g_dinv[n] = dinv;

    const float* xr = x + (size_t)n * DIN;
    float ax = 0.f, ay = 0.f, az = 0.f, aw = 0.f;
    #pragma unroll
    for (int k = 0; k < DIN; k++) {
        float xv = __ldg(xr + k);         // broadcast across the 8-thread group
        ax += xv * sW[k][j4 + 0];
        ay += xv * sW[k][j4 + 1];
        az += xv * sW[k][j4 + 2];
        aw += xv * sW[k][j4 + 3];
    }

    // stash projected row for the edge pass
    float4* yp = (float4*)(g_y + (size_t)n * DC + j4);
    *yp = make_float4(ax, ay, az, aw);

    // init output with self-loop term + bias
    float d2 = dinv * dinv;
    float4 o = make_float4(ax * d2 + sb[j4 + 0], ay * d2 + sb[j4 + 1],
                           az * d2 + sb[j4 + 2], aw * d2 + sb[j4 + 3]);
    float* obase = (j4 < DOUT)
        ? (out + (size_t)n * DOUT + j4)                               // mu half
        : (out + (size_t)NN * DOUT + (size_t)n * DOUT + (j4 - DOUT)); // logstd half
    *(float4*)obase = o;
}

// ---------------------------------------------------------------------------
// Kernel 4: edge scatter, 8 THREADS PER EDGE.
// Lane t of the 8-thread group owns float4 #t of the 32-col concatenated row:
//   - gather: threads 0..7 read contiguous 128B of g_y[src]  -> 1 line/edge
//   - scatter: one red.global.add.v4.f32 per thread into out[dst]
// This coalesces the former 8-wavefront-per-edge gather into 1.
// ---------------------------------------------------------------------------
__device__ __forceinline__ void red_add_v4(float* addr, float4 v) {
    asm volatile("red.global.add.v4.f32 [%0], {%1, %2, %3, %4};"
                 :: "l"(addr), "f"(v.x), "f"(v.y), "f"(v.z), "f"(v.w)
                 : "memory");
}

__global__ void k_edges(const int* __restrict__ src,
                        const int* __restrict__ dst,
                        float* __restrict__ out) {
    int g = blockIdx.x * blockDim.x + threadIdx.x;
    int e = g >> 3;             // edge
    int t = g & 7;              // float4 slot within the 32-col row
    if (e >= EE) return;

    int s = __ldg(src + e);     // same addr across the 8-lane group -> broadcast
    int d = __ldg(dst + e);
    float w = __ldg(&g_dinv[s]) * __ldg(&g_dinv[d]);

    float4 v = __ldg((const float4*)(g_y + (size_t)s * DC) + t);
    v.x *= w; v.y *= w; v.z *= w; v.w *= w;

    float* addr = (t < 4)
        ? (out + (size_t)d * DOUT + t * 4)                            // mu half
        : (out + (size_t)NN * DOUT + (size_t)d * DOUT + (t - 4) * 4); // logstd half
    red_add_v4(addr, v);
}

// ---------------------------------------------------------------------------
extern "C" void kernel_launch(void* const* d_in, const int* in_sizes, int n_in,
                              void* d_out, int out_size) {
    const float* x   = (const float*)d_in[0];
    const int*   ei  = (const int*)  d_in[1];   // (2, E): row 0 = src, row 1 = dst
    const float* Wmu = (const float*)d_in[2];
    const float* bmu = (const float*)d_in[3];
    const float* Wls = (const float*)d_in[4];
    const float* bls = (const float*)d_in[5];
    float* out = (float*)d_out;

    const int* src = ei;
    const int* dst = ei + EE;

    k_init_cnt<<<(NN + 255) / 256, 256>>>();
    k_count   <<<(EE + 255) / 256, 256>>>(dst);
    k_project <<<(NN * 8 + 255) / 256, 256>>>(x, Wmu, bmu, Wls, bls, out);
    k_edges   <<<((size_t)EE * 8 + 255) / 256, 256>>>(src, dst, out);
}

// round 3
// speedup vs baseline: 1.7297x; 1.1081x over previous
#include <cuda_runtime.h>
#include <cstdint>

#define NN   100000
#define EE   1600000
#define DIN  48
#define DOUT 16
#define DC   32                      // concatenated output dim (mu | logstd)
#define NBLK ((NN + 255) / 256)      // 391 scan blocks

// Scratch (allocation-free contract: __device__ globals)
__device__ unsigned int g_cnt[NN];      // in-degree (without self loop)
__device__ unsigned int g_base[NN];     // CSR row start (exclusive scan of cnt)
__device__ unsigned int g_cur[NN];      // scatter cursor (init = base)
__device__ unsigned int g_bsum[NBLK];   // per-block sums for scan
__device__ unsigned int g_boff[NBLK];   // scanned block offsets
__device__ int          g_esrc[EE];     // src indices sorted by dst
__device__ float        g_dinv[NN];
__device__ __align__(128) float g_y[(size_t)NN * DC];  // dinv*(x@[Wmu|Wls]); row = 128B

// ---------------------------------------------------------------------------
// 1: zero degree counters
// ---------------------------------------------------------------------------
__global__ void k_init_cnt() {
    int i = blockIdx.x * blockDim.x + threadIdx.x;
    if (i < NN) g_cnt[i] = 0u;
}

// ---------------------------------------------------------------------------
// 2: in-degree count on dst
// ---------------------------------------------------------------------------
__global__ void k_count(const int* __restrict__ dst) {
    int i = blockIdx.x * blockDim.x + threadIdx.x;
    if (i < EE) atomicAdd(&g_cnt[dst[i]], 1u);
}

// ---------------------------------------------------------------------------
// 3a: per-block exclusive scan of g_cnt -> g_base (block-local), block sums
// ---------------------------------------------------------------------------
__global__ void k_scanA() {
    __shared__ unsigned s[256];
    int tid = threadIdx.x;
    int i = blockIdx.x * 256 + tid;
    unsigned v = (i < NN) ? g_cnt[i] : 0u;
    s[tid] = v;
    __syncthreads();
    #pragma unroll
    for (int off = 1; off < 256; off <<= 1) {
        unsigned t = (tid >= off) ? s[tid - off] : 0u;
        __syncthreads();
        s[tid] += t;
        __syncthreads();
    }
    if (i < NN) g_base[i] = s[tid] - v;          // exclusive within block
    if (tid == 255) g_bsum[blockIdx.x] = s[255]; // block total
}

// ---------------------------------------------------------------------------
// 3b: scan the 391 block sums (single block, 512 threads)
// ---------------------------------------------------------------------------
__global__ void k_scanB() {
    __shared__ unsigned s[512];
    int tid = threadIdx.x;
    unsigned v = (tid < NBLK) ? g_bsum[tid] : 0u;
    s[tid] = v;
    __syncthreads();
    #pragma unroll
    for (int off = 1; off < 512; off <<= 1) {
        unsigned t = (tid >= off) ? s[tid - off] : 0u;
        __syncthreads();
        s[tid] += t;
        __syncthreads();
    }
    if (tid < NBLK) g_boff[tid] = s[tid] - v;    // exclusive
}

// ---------------------------------------------------------------------------
// 4: projection y' = dinv * (x @ Wcat); finalize base; init cursor; store dinv
//    8 threads per node, each producing a float4 (4 of the 32 cols).
// ---------------------------------------------------------------------------
__global__ void k_project(const float* __restrict__ x,
                          const float* __restrict__ Wmu,
                          const float* __restrict__ Wls) {
    __shared__ float sW[DIN][DC];   // 6 KB, concatenated weights, k-major

    int tid = threadIdx.x;  // 256
    for (int i = tid; i < DIN * DOUT; i += blockDim.x) {
        int k = i / DOUT, j = i % DOUT;
        sW[k][j]      = Wmu[i];
        sW[k][j + 16] = Wls[i];
    }
    __syncthreads();

    int g  = blockIdx.x * blockDim.x + tid;
    int n  = g >> 3;            // node
    int j4 = (g & 7) * 4;       // output column group
    if (n >= NN) return;

    float dinv = rsqrtf(1.0f + (float)g_cnt[n]);
    if ((g & 7) == 0) {
        g_dinv[n] = dinv;
        unsigned fb = g_base[n] + g_boff[n >> 8];  // add scanned block offset
        g_base[n] = fb;
        g_cur[n]  = fb;
    }

    const float* xr = x + (size_t)n * DIN;
    float ax = 0.f, ay = 0.f, az = 0.f, aw = 0.f;
    #pragma unroll
    for (int k = 0; k < DIN; k++) {
        float xv = __ldg(xr + k);         // broadcast across the 8-thread group
        ax += xv * sW[k][j4 + 0];
        ay += xv * sW[k][j4 + 1];
        az += xv * sW[k][j4 + 2];
        aw += xv * sW[k][j4 + 3];
    }
    float4* yp = (float4*)(g_y + (size_t)n * DC + j4);
    *yp = make_float4(ax * dinv, ay * dinv, az * dinv, aw * dinv);
}

// ---------------------------------------------------------------------------
// 5: counting-sort scatter: place src of each edge into its dst's CSR segment
// ---------------------------------------------------------------------------
__global__ void k_scatter(const int* __restrict__ src,
                          const int* __restrict__ dst) {
    int e = blockIdx.x * blockDim.x + threadIdx.x;
    if (e >= EE) return;
    int s = __ldg(src + e);
    int d = __ldg(dst + e);
    unsigned pos = atomicAdd(&g_cur[d], 1u);
    g_esrc[pos] = s;
}

// ---------------------------------------------------------------------------
// 6: aggregate, 8 THREADS PER NODE, no atomics.
//    acc = y'[n] (self) + sum over incoming edges y'[src];  out = dinv*acc + b
// ---------------------------------------------------------------------------
__global__ void k_agg(const float* __restrict__ bmu,
                      const float* __restrict__ bls,
                      float* __restrict__ out) {
    int g = blockIdx.x * blockDim.x + threadIdx.x;
    int n = g >> 3;             // node
    int t = g & 7;              // float4 slot within the 32-col row
    if (n >= NN) return;

    float4 acc = __ldg((const float4*)(g_y + (size_t)n * DC) + t);  // self term

    unsigned start = g_base[n];
    unsigned deg   = g_cnt[n];
    const int* ep  = g_esrc + start;

    unsigned i = 0;
    for (; i + 2 <= deg; i += 2) {                 // 2-way unroll for MLP
        int s0 = __ldg(ep + i);
        int s1 = __ldg(ep + i + 1);
        float4 v0 = __ldg((const float4*)(g_y + (size_t)s0 * DC) + t);
        float4 v1 = __ldg((const float4*)(g_y + (size_t)s1 * DC) + t);
        acc.x += v0.x + v1.x;  acc.y += v0.y + v1.y;
        acc.z += v0.z + v1.z;  acc.w += v0.w + v1.w;
    }
    if (i < deg) {
        int s0 = __ldg(ep + i);
        float4 v0 = __ldg((const float4*)(g_y + (size_t)s0 * DC) + t);
        acc.x += v0.x;  acc.y += v0.y;  acc.z += v0.z;  acc.w += v0.w;
    }

    float dn = g_dinv[n];
    int col = (t & 3) * 4;
    const float* bp = (t < 4) ? (bmu + col) : (bls + col);
    float4 o = make_float4(acc.x * dn + __ldg(bp + 0),
                           acc.y * dn + __ldg(bp + 1),
                           acc.z * dn + __ldg(bp + 2),
                           acc.w * dn + __ldg(bp + 3));
    float* obase = (t < 4)
        ? (out + (size_t)n * DOUT + col)                               // mu half
        : (out + (size_t)NN * DOUT + (size_t)n * DOUT + col);          // logstd half
    *(float4*)obase = o;
}

// ---------------------------------------------------------------------------
extern "C" void kernel_launch(void* const* d_in, const int* in_sizes, int n_in,
                              void* d_out, int out_size) {
    const float* x   = (const float*)d_in[0];
    const int*   ei  = (const int*)  d_in[1];   // (2, E): row 0 = src, row 1 = dst
    const float* Wmu = (const float*)d_in[2];
    const float* bmu = (const float*)d_in[3];
    const float* Wls = (const float*)d_in[4];
    const float* bls = (const float*)d_in[5];
    float* out = (float*)d_out;

    const int* src = ei;
    const int* dst = ei + EE;

    k_init_cnt<<<(NN + 255) / 256, 256>>>();
    k_count   <<<(EE + 255) / 256, 256>>>(dst);
    k_scanA   <<<NBLK, 256>>>();
    k_scanB   <<<1, 512>>>();
    k_project <<<(NN * 8 + 255) / 256, 256>>>(x, Wmu, Wls);
    k_scatter <<<(EE + 255) / 256, 256>>>(src, dst);
    k_agg     <<<(NN * 8 + 255) / 256, 256>>>(bmu, bls, out);
}

// round 4
// speedup vs baseline: 1.8565x; 1.0733x over previous
#include <cuda_runtime.h>
#include <cuda_fp16.h>
#include <cstdint>

#define NN   100000
#define EE   1600000
#define DIN  48
#define DOUT 16
#define DC   32                      // concatenated output dim (mu | logstd)
#define NBLK ((NN + 255) / 256)      // 391 scan blocks

// Scratch (allocation-free contract: __device__ globals)
__device__ unsigned int g_cnt[NN];      // in-degree (without self loop)
__device__ unsigned int g_base[NN];     // CSR row start (exclusive scan of cnt)
__device__ unsigned int g_cur[NN];      // scatter cursor (init = base)
__device__ unsigned int g_bsum[NBLK];   // per-block sums for scan
__device__ unsigned int g_boff[NBLK];   // scanned block offsets
__device__ int          g_esrc[EE];     // src indices sorted by dst
__device__ float        g_dinv[NN];
__device__ __align__(128) __half g_y[(size_t)NN * DC];  // dinv*(x@[Wmu|Wls]) fp16; row = 64B

// ---------------------------------------------------------------------------
// 1: zero degree counters
// ---------------------------------------------------------------------------
__global__ void k_init_cnt() {
    int i = blockIdx.x * blockDim.x + threadIdx.x;
    if (i < NN) g_cnt[i] = 0u;
}

// ---------------------------------------------------------------------------
// 2: in-degree count on dst
// ---------------------------------------------------------------------------
__global__ void k_count(const int* __restrict__ dst) {
    int i = blockIdx.x * blockDim.x + threadIdx.x;
    if (i < EE) atomicAdd(&g_cnt[dst[i]], 1u);
}

// ---------------------------------------------------------------------------
// 3a: per-block exclusive scan of g_cnt -> g_base (block-local) + block sums
// ---------------------------------------------------------------------------
__global__ void k_scanA() {
    __shared__ unsigned ws[8];
    int tid = threadIdx.x;                  // 256
    int i = blockIdx.x * 256 + tid;
    unsigned v = (i < NN) ? g_cnt[i] : 0u;
    unsigned xs = v;
    #pragma unroll
    for (int o = 1; o < 32; o <<= 1) {      // warp inclusive scan
        unsigned t = __shfl_up_sync(0xffffffffu, xs, o);
        if ((tid & 31) >= o) xs += t;
    }
    if ((tid & 31) == 31) ws[tid >> 5] = xs;
    __syncthreads();
    if (tid < 32) {
        unsigned w = (tid < 8) ? ws[tid] : 0u;
        #pragma unroll
        for (int o = 1; o < 8; o <<= 1) {
            unsigned t = __shfl_up_sync(0xffffffffu, w, o);
            if (tid >= o) w += t;
        }
        if (tid < 8) ws[tid] = w;           // inclusive over warp sums
    }
    __syncthreads();
    unsigned woff = (tid >> 5) ? ws[(tid >> 5) - 1] : 0u;
    if (i < NN) g_base[i] = xs - v + woff;           // exclusive within block
    if (tid == 255) g_bsum[blockIdx.x] = xs + woff;  // block total
}

// ---------------------------------------------------------------------------
// 3b: scan the 391 block sums (single block, 512 threads, warp shuffles)
// ---------------------------------------------------------------------------
__global__ void k_scanB() {
    __shared__ unsigned ws[16];
    int tid = threadIdx.x;                  // 512
    unsigned v = (tid < NBLK) ? g_bsum[tid] : 0u;
    unsigned xs = v;
    #pragma unroll
    for (int o = 1; o < 32; o <<= 1) {
        unsigned t = __shfl_up_sync(0xffffffffu, xs, o);
        if ((tid & 31) >= o) xs += t;
    }
    if ((tid & 31) == 31) ws[tid >> 5] = xs;
    __syncthreads();
    if (tid < 32) {
        unsigned w = (tid < 16) ? ws[tid] : 0u;
        #pragma unroll
        for (int o = 1; o < 16; o <<= 1) {
            unsigned t = __shfl_up_sync(0xffffffffu, w, o);
            if (tid >= o) w += t;
        }
        if (tid < 16) ws[tid] = w;
    }
    __syncthreads();
    unsigned woff = (tid >> 5) ? ws[(tid >> 5) - 1] : 0u;
    if (tid < NBLK) g_boff[tid] = xs - v + woff;     // exclusive
}

// ---------------------------------------------------------------------------
// 3c: finalize CSR base (add scanned block offsets), init scatter cursor
// ---------------------------------------------------------------------------
__global__ void k_fin() {
    int i = blockIdx.x * blockDim.x + threadIdx.x;
    if (i >= NN) return;
    unsigned fb = g_base[i] + g_boff[i >> 8];
    g_base[i] = fb;
    g_cur[i]  = fb;
}

// ---------------------------------------------------------------------------
// 4: projection y' = dinv * (x @ Wcat) stored fp16; also store dinv.
//    Depends ONLY on g_cnt -> runs on side stream, overlapped with the scans.
//    8 threads per node, each producing 4 of the 32 cols.
// ---------------------------------------------------------------------------
__global__ void k_project(const float* __restrict__ x,
                          const float* __restrict__ Wmu,
                          const float* __restrict__ Wls) {
    __shared__ float sW[DIN][DC];   // 6 KB, concatenated weights, k-major

    int tid = threadIdx.x;  // 256
    for (int i = tid; i < DIN * DOUT; i += blockDim.x) {
        int k = i / DOUT, j = i % DOUT;
        sW[k][j]      = Wmu[i];
        sW[k][j + 16] = Wls[i];
    }
    __syncthreads();

    int g  = blockIdx.x * blockDim.x + tid;
    int n  = g >> 3;            // node
    int j4 = (g & 7) * 4;       // output column group
    if (n >= NN) return;

    float dinv = rsqrtf(1.0f + (float)g_cnt[n]);
    if ((g & 7) == 0) g_dinv[n] = dinv;

    const float* xr = x + (size_t)n * DIN;
    float ax = 0.f, ay = 0.f, az = 0.f, aw = 0.f;
    #pragma unroll
    for (int k = 0; k < DIN; k++) {
        float xv = __ldg(xr + k);         // broadcast across the 8-thread group
        ax += xv * sW[k][j4 + 0];
        ay += xv * sW[k][j4 + 1];
        az += xv * sW[k][j4 + 2];
        aw += xv * sW[k][j4 + 3];
    }
    __half2 h0 = __floats2half2_rn(ax * dinv, ay * dinv);
    __half2 h1 = __floats2half2_rn(az * dinv, aw * dinv);
    uint2 u;
    u.x = *reinterpret_cast<unsigned*>(&h0);
    u.y = *reinterpret_cast<unsigned*>(&h1);
    *((uint2*)(g_y + (size_t)n * DC + j4)) = u;   // 8B store
}

// ---------------------------------------------------------------------------
// 5: counting-sort scatter: place src of each edge into its dst's CSR segment
// ---------------------------------------------------------------------------
__global__ void k_scatter(const int* __restrict__ src,
                          const int* __restrict__ dst) {
    int e = blockIdx.x * blockDim.x + threadIdx.x;
    if (e >= EE) return;
    int s = __ldg(src + e);
    int d = __ldg(dst + e);
    unsigned pos = atomicAdd(&g_cur[d], 1u);
    g_esrc[pos] = s;
}

// ---------------------------------------------------------------------------
// 6: aggregate, 8 THREADS PER NODE, no atomics, fp16 gathers, fp32 accum.
//    acc = y'[n] (self) + sum over incoming edges y'[src];  out = dinv*acc + b
// ---------------------------------------------------------------------------
__device__ __forceinline__ float4 ld_row4(int node, int t) {
    uint2 u = __ldg((const uint2*)(g_y + (size_t)node * DC) + t);
    __half2 h0 = *reinterpret_cast<__half2*>(&u.x);
    __half2 h1 = *reinterpret_cast<__half2*>(&u.y);
    float2 f0 = __half22float2(h0);
    float2 f1 = __half22float2(h1);
    return make_float4(f0.x, f0.y, f1.x, f1.y);
}

__global__ void k_agg(const float* __restrict__ bmu,
                      const float* __restrict__ bls,
                      float* __restrict__ out) {
    int g = blockIdx.x * blockDim.x + threadIdx.x;
    int n = g >> 3;             // node
    int t = g & 7;              // 4-col slot within the 32-col row
    if (n >= NN) return;

    float4 acc = ld_row4(n, t);         // self term (already dinv-scaled)

    unsigned start = g_base[n];
    unsigned deg   = g_cnt[n];
    const int* ep  = g_esrc + start;

    unsigned i = 0;
    for (; i + 4 <= deg; i += 4) {                 // 4-way unroll for MLP
        int s0 = __ldg(ep + i), s1 = __ldg(ep + i + 1);
        int s2 = __ldg(ep + i + 2), s3 = __ldg(ep + i + 3);
        float4 v0 = ld_row4(s0, t), v1 = ld_row4(s1, t);
        float4 v2 = ld_row4(s2, t), v3 = ld_row4(s3, t);
        acc.x += (v0.x + v1.x) + (v2.x + v3.x);
        acc.y += (v0.y + v1.y) + (v2.y + v3.y);
        acc.z += (v0.z + v1.z) + (v2.z + v3.z);
        acc.w += (v0.w + v1.w) + (v2.w + v3.w);
    }
    for (; i < deg; i++) {
        float4 v0 = ld_row4(__ldg(ep + i), t);
        acc.x += v0.x;  acc.y += v0.y;  acc.z += v0.z;  acc.w += v0.w;
    }

    float dn = g_dinv[n];
    int col = (t & 3) * 4;
    const float* bp = (t < 4) ? (bmu + col) : (bls + col);
    float4 o = make_float4(acc.x * dn + __ldg(bp + 0),
                           acc.y * dn + __ldg(bp + 1),
                           acc.z * dn + __ldg(bp + 2),
                           acc.w * dn + __ldg(bp + 3));
    float* obase = (t < 4)
        ? (out + (size_t)n * DOUT + col)                       // mu half
        : (out + (size_t)NN * DOUT + (size_t)n * DOUT + col);  // logstd half
    *(float4*)obase = o;
}

// ---------------------------------------------------------------------------
// Host: side stream + events created at static init (host objects only; no
// device-memory allocation). Used for forked capture: project runs
// concurrently with the scan chain.
// ---------------------------------------------------------------------------
static cudaStream_t g_s2 = nullptr;
static cudaEvent_t  g_evFork = nullptr, g_evJoin = nullptr;
static struct StreamInit {
    StreamInit() {
        cudaStreamCreateWithFlags(&g_s2, cudaStreamNonBlocking);
        cudaEventCreateWithFlags(&g_evFork, cudaEventDisableTiming);
        cudaEventCreateWithFlags(&g_evJoin, cudaEventDisableTiming);
    }
} g_streamInit;

extern "C" void kernel_launch(void* const* d_in, const int* in_sizes, int n_in,
                              void* d_out, int out_size) {
    const float* x   = (const float*)d_in[0];
    const int*   ei  = (const int*)  d_in[1];   // (2, E): row 0 = src, row 1 = dst
    const float* Wmu = (const float*)d_in[2];
    const float* bmu = (const float*)d_in[3];
    const float* Wls = (const float*)d_in[4];
    const float* bls = (const float*)d_in[5];
    float* out = (float*)d_out;

    const int* src = ei;
    const int* dst = ei + EE;

    k_init_cnt<<<(NN + 255) / 256, 256>>>();
    k_count   <<<(EE + 255) / 256, 256>>>(dst);

    bool forked = (g_s2 && g_evFork && g_evJoin);
    if (forked) {
        // fork: project (depends only on g_cnt) overlaps the scan chain
        cudaEventRecord(g_evFork, 0);
        cudaStreamWaitEvent(g_s2, g_evFork, 0);
        k_project<<<(NN * 8 + 255) / 256, 256, 0, g_s2>>>(x, Wmu, Wls);
    }
    k_scanA<<<NBLK, 256>>>();
    k_scanB<<<1, 512>>>();
    k_fin  <<<(NN + 255) / 256, 256>>>();
    if (forked) {
        cudaEventRecord(g_evJoin, g_s2);
        cudaStreamWaitEvent(0, g_evJoin, 0);
    } else {
        k_project<<<(NN * 8 + 255) / 256, 256>>>(x, Wmu, Wls);
    }
    k_scatter<<<(EE + 255) / 256, 256>>>(src, dst);
    k_agg    <<<(NN * 8 + 255) / 256, 256>>>(bmu, bls, out);
}